// round 4
// baseline (speedup 1.0000x reference)
#include <cuda_runtime.h>
#include <cuda_bf16.h>
#include <stdint.h>

#define EPSF 1e-6f
#define TPB 256
#define MAX_BLOCKS 4096

__device__ double g_part[MAX_BLOCKS];
__device__ unsigned int g_ticket = 0;   // zero at module load; reset by last block

template<int W>
__global__ void __launch_bounds__(TPB) runway_loss_kernel(
        const float* __restrict__ pred,
        const unsigned char* __restrict__ mask,
        const float* __restrict__ runway,
        float* __restrict__ out,
        int B) {
    constexpr int H = 4 * W;
    __shared__ uint32_t sm[W * TPB];

    int s0 = blockIdx.x * TPB;
    int nsmp = B - s0; if (nsmp > TPB) nsmp = TPB;
    int nwords = nsmp * W;

    // Coalesced staging of this block's mask slab into smem.
    const uint32_t* mw = (const uint32_t*)mask + (size_t)s0 * W;
    if ((nwords & 3) == 0 && ((((unsigned long long)mw) & 15ULL) == 0ULL)) {
        const uint4* mv = (const uint4*)mw;
        uint4* sv = (uint4*)sm;
        int nvec = nwords >> 2;
        for (int i = threadIdx.x; i < nvec; i += TPB) sv[i] = mv[i];
    } else {
        for (int i = threadIdx.x; i < nwords; i += TPB) sm[i] = mw[i];
    }
    __syncthreads();

    float contrib = 0.0f;
    int s = s0 + threadIdx.x;
    if (threadIdx.x < nsmp) {
        const uint32_t* row = sm + threadIdx.x * W;
        int ones = 0;
        #pragma unroll
        for (int j = 0; j < W; j++) ones += __popc(row[j]);
        int L = H - ones;                      // valid length

        float rx = runway[(size_t)s * 4 + 2];
        float ry = runway[(size_t)s * 4 + 3];
        float rn = sqrtf(rx * rx + ry * ry) + EPSF;
        rx /= rn; ry /= rn;

        const float* prow = pred + (size_t)s * H * 3;
        float px[4], py[4];
        #pragma unroll
        for (int j = 0; j < 4; j++) {
            int idx = L - 4 + j;
            if (idx < 0) idx = 0;
            if (idx > H - 1) idx = H - 1;
            px[j] = prow[idx * 3 + 0];
            py[j] = prow[idx * 3 + 1];
        }

        float acc = 0.0f;
        #pragma unroll
        for (int j = 0; j < 3; j++) {
            float dx = px[j + 1] - px[j];
            float dy = py[j + 1] - py[j];
            float dn = sqrtf(dx * dx + dy * dy) + EPSF;
            float cs = (dx * rx + dy * ry) / dn;
            float t  = 1.0f - cs;
            acc += t * t;
        }
        contrib = acc * (1.0f / 3.0f);
    }

    // ---- block reduction (fp32 tree, fixed order) ----
    __shared__ float red[TPB];
    red[threadIdx.x] = contrib;
    __syncthreads();
    #pragma unroll
    for (int o = TPB / 2; o >= 32; o >>= 1) {
        if (threadIdx.x < o) red[threadIdx.x] += red[threadIdx.x + o];
        __syncthreads();
    }
    __shared__ bool s_last;
    if (threadIdx.x < 32) {
        float v = red[threadIdx.x];
        #pragma unroll
        for (int o = 16; o; o >>= 1)
            v += __shfl_xor_sync(0xFFFFFFFFu, v, o);
        if (threadIdx.x == 0) {
            g_part[blockIdx.x] = (double)v;
            __threadfence();
            unsigned int t = atomicAdd(&g_ticket, 1u);
            s_last = (t == gridDim.x - 1);
        }
    }
    __syncthreads();

    // ---- last block finalizes: fixed-order double reduction of partials ----
    if (s_last) {
        __shared__ double dred[TPB];
        double dv = 0.0;
        for (int i = threadIdx.x; i < (int)gridDim.x; i += TPB)
            dv += g_part[i];
        dred[threadIdx.x] = dv;
        __syncthreads();
        #pragma unroll
        for (int o = TPB / 2; o >= 1; o >>= 1) {
            if (threadIdx.x < o) dred[threadIdx.x] += dred[threadIdx.x + o];
            __syncthreads();
        }
        if (threadIdx.x == 0) {
            out[0] = (float)(dred[0] / (double)B);
            g_ticket = 0;                      // reset for next graph replay
        }
    }
}

// Generic fallback for unexpected H (same single-launch pattern).
__global__ void __launch_bounds__(TPB) runway_loss_generic(
        const float* __restrict__ pred,
        const unsigned char* __restrict__ mask,
        const float* __restrict__ runway,
        float* __restrict__ out,
        int B, int H) {
    int s = blockIdx.x * blockDim.x + threadIdx.x;
    float contrib = 0.0f;
    if (s < B) {
        const unsigned char* mrow = mask + (size_t)s * H;
        int ones = 0;
        for (int i = 0; i < H; i++) ones += (int)mrow[i];
        int L = H - ones;
        float rx = runway[(size_t)s * 4 + 2];
        float ry = runway[(size_t)s * 4 + 3];
        float rn = sqrtf(rx * rx + ry * ry) + EPSF;
        rx /= rn; ry /= rn;
        const float* prow = pred + (size_t)s * H * 3;
        float px[4], py[4];
        for (int j = 0; j < 4; j++) {
            int idx = L - 4 + j;
            if (idx < 0) idx = 0;
            if (idx > H - 1) idx = H - 1;
            px[j] = prow[idx * 3 + 0];
            py[j] = prow[idx * 3 + 1];
        }
        float acc = 0.0f;
        for (int j = 0; j < 3; j++) {
            float dx = px[j + 1] - px[j];
            float dy = py[j + 1] - py[j];
            float dn = sqrtf(dx * dx + dy * dy) + EPSF;
            float cs = (dx * rx + dy * ry) / dn;
            float t  = 1.0f - cs;
            acc += t * t;
        }
        contrib = acc * (1.0f / 3.0f);
    }
    __shared__ float red[TPB];
    red[threadIdx.x] = contrib;
    __syncthreads();
    for (int o = TPB / 2; o >= 32; o >>= 1) {
        if (threadIdx.x < o) red[threadIdx.x] += red[threadIdx.x + o];
        __syncthreads();
    }
    __shared__ bool s_last;
    if (threadIdx.x < 32) {
        float v = red[threadIdx.x];
        for (int o = 16; o; o >>= 1)
            v += __shfl_xor_sync(0xFFFFFFFFu, v, o);
        if (threadIdx.x == 0) {
            g_part[blockIdx.x] = (double)v;
            __threadfence();
            unsigned int t = atomicAdd(&g_ticket, 1u);
            s_last = (t == gridDim.x - 1);
        }
    }
    __syncthreads();
    if (s_last) {
        __shared__ double dred[TPB];
        double dv = 0.0;
        for (int i = threadIdx.x; i < (int)gridDim.x; i += TPB)
            dv += g_part[i];
        dred[threadIdx.x] = dv;
        __syncthreads();
        for (int o = TPB / 2; o >= 1; o >>= 1) {
            if (threadIdx.x < o) dred[threadIdx.x] += dred[threadIdx.x + o];
            __syncthreads();
        }
        if (threadIdx.x == 0) {
            out[0] = (float)(dred[0] / (double)B);
            g_ticket = 0;
        }
    }
}

extern "C" void kernel_launch(void* const* d_in, const int* in_sizes, int n_in,
                              void* d_out, int out_size) {
    const float*         pred   = (const float*)d_in[0];
    // d_in[1] = target_abs (unused by the reference)
    const unsigned char* mask   = (const unsigned char*)d_in[2];
    const float*         runway = (const float*)d_in[3];
    float*               out    = (float*)d_out;

    int B = in_sizes[3] / 4;          // runway is (B, 4)
    int H = in_sizes[2] / B;          // mask is (B, H)

    int blocks = (B + TPB - 1) / TPB;
    if (blocks > MAX_BLOCKS) blocks = MAX_BLOCKS;   // safety (B<=1M); B=65536 -> 256

    if (H == 120 && blocks * TPB >= B) {
        runway_loss_kernel<30><<<blocks, TPB>>>(pred, mask, runway, out, B);
    } else {
        // grid-stride not implemented; fall back covers all B with enough blocks
        int gblocks = (B + TPB - 1) / TPB;
        runway_loss_generic<<<gblocks, TPB>>>(pred, mask, runway, out, B, H);
    }
}

// round 5
// speedup vs baseline: 1.2179x; 1.2179x over previous
#include <cuda_runtime.h>
#include <cuda_bf16.h>
#include <stdint.h>

#define EPSF 1e-6f
#define TPB 256

__device__ double g_acc;   // zero at module load; reset by finalize each call

__global__ void finalize_kernel(float* out, int B) {
    out[0] = (float)(g_acc / (double)B);
    g_acc = 0.0;
}

// 4 lanes cooperate per sample. H = 120 specialization.
__global__ void __launch_bounds__(TPB) runway_loss_h120(
        const float* __restrict__ pred,
        const unsigned char* __restrict__ mask,
        const float* __restrict__ runway,
        int B) {
    const unsigned FULL = 0xFFFFFFFFu;
    int t   = blockIdx.x * TPB + threadIdx.x;
    int g   = t >> 2;          // sample index
    int sub = t & 3;           // lane within 4-lane group
    bool active = (g < B);

    float per = 0.0f;          // per-sample contribution (sub==0 lanes only)

    // ---- mask popcount: each lane reads up to 4 uint2 (8B-aligned, 120B rows) ----
    int ones = 0;
    float px = 0.0f, py = 0.0f;
    if (active) {
        const uint2* row = (const uint2*)(mask + (size_t)g * 120);
        int base = sub * 4;                 // uint2 index: 0,4,8,12 (15 total)
        uint2 a = row[base];
        uint2 b = row[base + 1];
        uint2 c = row[base + 2];
        uint2 d = make_uint2(0u, 0u);
        if (base + 3 < 15) d = row[base + 3];   // lane 3 reads only 3 words
        ones = __popc(a.x) + __popc(a.y) + __popc(b.x) + __popc(b.y)
             + __popc(c.x) + __popc(c.y) + __popc(d.x) + __popc(d.y);
    }
    // group reduce (4-lane groups are xor-closed under offsets 1,2)
    ones += __shfl_xor_sync(FULL, ones, 1);
    ones += __shfl_xor_sync(FULL, ones, 2);

    if (active) {
        int L = 120 - ones;                // valid length (>= 5 by construction)
        int idx = L - 4 + sub;
        if (idx < 0) idx = 0;
        if (idx > 119) idx = 119;
        const float* p = pred + (size_t)g * 360 + idx * 3;
        px = p[0];
        py = p[1];
    }

    // neighbor point (lane sub gets lane sub+1's point; lane 3 result unused)
    float nx = __shfl_down_sync(FULL, px, 1);
    float ny = __shfl_down_sync(FULL, py, 1);

    float term = 0.0f;
    if (active && sub < 3) {
        float rx = runway[(size_t)g * 4 + 2];
        float ry = runway[(size_t)g * 4 + 3];
        float rn = __fsqrt_rn(rx * rx + ry * ry) + EPSF;
        rx = __fdiv_rn(rx, rn);
        ry = __fdiv_rn(ry, rn);

        float dx = nx - px;
        float dy = ny - py;
        float dn = __fsqrt_rn(dx * dx + dy * dy) + EPSF;
        float cs = __fdiv_rn(dx, dn) * rx + __fdiv_rn(dy, dn) * ry;
        float u  = 1.0f - cs;
        term = u * u;
    }
    term += __shfl_xor_sync(FULL, term, 1);
    term += __shfl_xor_sync(FULL, term, 2);
    if (active && sub == 0)
        per = __fdiv_rn(term, 3.0f);       // mean over 3 directions

    // ---- warp reduce (sub!=0 lanes hold 0) ----
    per += __shfl_xor_sync(FULL, per, 4);
    per += __shfl_xor_sync(FULL, per, 8);
    per += __shfl_xor_sync(FULL, per, 16);

    // ---- block reduce: one double atomic per block ----
    __shared__ float wsum[TPB / 32];
    int lane = threadIdx.x & 31;
    int wid  = threadIdx.x >> 5;
    if (lane == 0) wsum[wid] = per;
    __syncthreads();
    if (threadIdx.x == 0) {
        float bsum = 0.0f;
        #pragma unroll
        for (int i = 0; i < TPB / 32; i++) bsum += wsum[i];
        atomicAdd(&g_acc, (double)bsum);
    }
}

// Generic fallback (thread-per-sample) for unexpected H.
__global__ void __launch_bounds__(TPB) runway_loss_generic(
        const float* __restrict__ pred,
        const unsigned char* __restrict__ mask,
        const float* __restrict__ runway,
        int B, int H) {
    int s = blockIdx.x * blockDim.x + threadIdx.x;
    float contrib = 0.0f;
    if (s < B) {
        const unsigned char* mrow = mask + (size_t)s * H;
        int ones = 0;
        for (int i = 0; i < H; i++) ones += (int)mrow[i];
        int L = H - ones;
        float rx = runway[(size_t)s * 4 + 2];
        float ry = runway[(size_t)s * 4 + 3];
        float rn = __fsqrt_rn(rx * rx + ry * ry) + EPSF;
        rx = __fdiv_rn(rx, rn);
        ry = __fdiv_rn(ry, rn);
        const float* prow = pred + (size_t)s * H * 3;
        float px[4], py[4];
        for (int j = 0; j < 4; j++) {
            int idx = L - 4 + j;
            if (idx < 0) idx = 0;
            if (idx > H - 1) idx = H - 1;
            px[j] = prow[idx * 3 + 0];
            py[j] = prow[idx * 3 + 1];
        }
        float acc = 0.0f;
        for (int j = 0; j < 3; j++) {
            float dx = px[j + 1] - px[j];
            float dy = py[j + 1] - py[j];
            float dn = __fsqrt_rn(dx * dx + dy * dy) + EPSF;
            float cs = __fdiv_rn(dx, dn) * rx + __fdiv_rn(dy, dn) * ry;
            float u  = 1.0f - cs;
            acc += u * u;
        }
        contrib = __fdiv_rn(acc, 3.0f);
    }
    __shared__ float red[TPB];
    red[threadIdx.x] = contrib;
    __syncthreads();
    for (int o = TPB / 2; o >= 32; o >>= 1) {
        if (threadIdx.x < o) red[threadIdx.x] += red[threadIdx.x + o];
        __syncthreads();
    }
    if (threadIdx.x < 32) {
        float v = red[threadIdx.x];
        for (int o = 16; o; o >>= 1)
            v += __shfl_xor_sync(0xFFFFFFFFu, v, o);
        if (threadIdx.x == 0)
            atomicAdd(&g_acc, (double)v);
    }
}

extern "C" void kernel_launch(void* const* d_in, const int* in_sizes, int n_in,
                              void* d_out, int out_size) {
    const float*         pred   = (const float*)d_in[0];
    // d_in[1] = target_abs (unused by the reference)
    const unsigned char* mask   = (const unsigned char*)d_in[2];
    const float*         runway = (const float*)d_in[3];
    float*               out    = (float*)d_out;

    int B = in_sizes[3] / 4;          // runway is (B, 4)
    int H = in_sizes[2] / B;          // mask is (B, H)

    if (H == 120) {
        int threads_needed = B * 4;
        int blocks = (threads_needed + TPB - 1) / TPB;
        runway_loss_h120<<<blocks, TPB>>>(pred, mask, runway, B);
    } else {
        int blocks = (B + TPB - 1) / TPB;
        runway_loss_generic<<<blocks, TPB>>>(pred, mask, runway, B, H);
    }
    finalize_kernel<<<1, 1>>>(out, B);
}

// round 6
// speedup vs baseline: 1.2593x; 1.0340x over previous
#include <cuda_runtime.h>
#include <cuda_bf16.h>
#include <stdint.h>

#define EPSF 1e-6f
#define TPB 256

__device__ double g_acc = 0.0;          // reset by last block every call
__device__ unsigned int g_ticket = 0;   // reset by last block every call

// 4 lanes cooperate per sample. H = 120 specialization. Single launch:
// last block to finish writes out[0] and resets the accumulators.
__global__ void __launch_bounds__(TPB) runway_loss_h120(
        const float* __restrict__ pred,
        const unsigned char* __restrict__ mask,
        const float* __restrict__ runway,
        float* __restrict__ out,
        int B) {
    const unsigned FULL = 0xFFFFFFFFu;
    int t   = blockIdx.x * TPB + threadIdx.x;
    int g   = t >> 2;          // sample index
    int sub = t & 3;           // lane within 4-lane group
    bool active = (g < B);

    float per = 0.0f;          // per-sample contribution (sub==0 lanes only)

    // ---- mask popcount: each lane reads up to 4 uint2 (8B-aligned, 120B rows) ----
    int ones = 0;
    float px = 0.0f, py = 0.0f;
    if (active) {
        const uint2* row = (const uint2*)(mask + (size_t)g * 120);
        int base = sub * 4;                     // uint2 index: 0,4,8,12 (15 total)
        uint2 a = row[base];
        uint2 b = row[base + 1];
        uint2 c = row[base + 2];
        uint2 d = make_uint2(0u, 0u);
        if (base + 3 < 15) d = row[base + 3];   // lane 3 reads only 3 words
        ones = __popc(a.x) + __popc(a.y) + __popc(b.x) + __popc(b.y)
             + __popc(c.x) + __popc(c.y) + __popc(d.x) + __popc(d.y);
    }
    // group reduce (4-lane groups are xor-closed under offsets 1,2)
    ones += __shfl_xor_sync(FULL, ones, 1);
    ones += __shfl_xor_sync(FULL, ones, 2);

    float2 rdir = make_float2(0.0f, 0.0f);
    if (active) {
        int L = 120 - ones;                     // valid length
        int idx = L - 4 + sub;
        if (idx < 0) idx = 0;
        if (idx > 119) idx = 119;
        const float* p = pred + (size_t)g * 360 + idx * 3;
        px = p[0];
        py = p[1];
        rdir = *(const float2*)(runway + (size_t)g * 4 + 2);
    }

    // neighbor point (lane sub gets lane sub+1's point; lane 3 result unused)
    float nx = __shfl_down_sync(FULL, px, 1);
    float ny = __shfl_down_sync(FULL, py, 1);

    float term = 0.0f;
    if (active && sub < 3) {
        float rx = rdir.x, ry = rdir.y;
        float rn = __fsqrt_rn(rx * rx + ry * ry) + EPSF;
        rx = __fdiv_rn(rx, rn);
        ry = __fdiv_rn(ry, rn);

        float dx = nx - px;
        float dy = ny - py;
        float dn = __fsqrt_rn(dx * dx + dy * dy) + EPSF;
        float cs = __fdiv_rn(dx, dn) * rx + __fdiv_rn(dy, dn) * ry;
        float u  = 1.0f - cs;
        term = u * u;
    }
    term += __shfl_xor_sync(FULL, term, 1);
    term += __shfl_xor_sync(FULL, term, 2);
    if (active && sub == 0)
        per = __fdiv_rn(term, 3.0f);            // mean over 3 directions

    // ---- warp reduce (sub!=0 lanes hold 0) ----
    per += __shfl_xor_sync(FULL, per, 4);
    per += __shfl_xor_sync(FULL, per, 8);
    per += __shfl_xor_sync(FULL, per, 16);

    // ---- block reduce: one double atomic per block, then last-block finalize ----
    __shared__ float wsum[TPB / 32];
    int lane = threadIdx.x & 31;
    int wid  = threadIdx.x >> 5;
    if (lane == 0) wsum[wid] = per;
    __syncthreads();
    if (threadIdx.x == 0) {
        float bsum = 0.0f;
        #pragma unroll
        for (int i = 0; i < TPB / 32; i++) bsum += wsum[i];
        atomicAdd(&g_acc, (double)bsum);
        __threadfence();
        unsigned int tkt = atomicAdd(&g_ticket, 1u);
        if (tkt == gridDim.x - 1) {
            // all blocks' g_acc additions are visible (they precede their
            // ticket increments, each ordered by __threadfence)
            out[0] = (float)(g_acc / (double)B);
            g_acc = 0.0;
            g_ticket = 0;
        }
    }
}

// Generic fallback (thread-per-sample) for unexpected H. Same single-launch pattern.
__global__ void __launch_bounds__(TPB) runway_loss_generic(
        const float* __restrict__ pred,
        const unsigned char* __restrict__ mask,
        const float* __restrict__ runway,
        float* __restrict__ out,
        int B, int H) {
    int s = blockIdx.x * blockDim.x + threadIdx.x;
    float contrib = 0.0f;
    if (s < B) {
        const unsigned char* mrow = mask + (size_t)s * H;
        int ones = 0;
        for (int i = 0; i < H; i++) ones += (int)mrow[i];
        int L = H - ones;
        float rx = runway[(size_t)s * 4 + 2];
        float ry = runway[(size_t)s * 4 + 3];
        float rn = __fsqrt_rn(rx * rx + ry * ry) + EPSF;
        rx = __fdiv_rn(rx, rn);
        ry = __fdiv_rn(ry, rn);
        const float* prow = pred + (size_t)s * H * 3;
        float px[4], py[4];
        for (int j = 0; j < 4; j++) {
            int idx = L - 4 + j;
            if (idx < 0) idx = 0;
            if (idx > H - 1) idx = H - 1;
            px[j] = prow[idx * 3 + 0];
            py[j] = prow[idx * 3 + 1];
        }
        float acc = 0.0f;
        for (int j = 0; j < 3; j++) {
            float dx = px[j + 1] - px[j];
            float dy = py[j + 1] - py[j];
            float dn = __fsqrt_rn(dx * dx + dy * dy) + EPSF;
            float cs = __fdiv_rn(dx, dn) * rx + __fdiv_rn(dy, dn) * ry;
            float u  = 1.0f - cs;
            acc += u * u;
        }
        contrib = __fdiv_rn(acc, 3.0f);
    }
    __shared__ float red[TPB];
    red[threadIdx.x] = contrib;
    __syncthreads();
    for (int o = TPB / 2; o >= 32; o >>= 1) {
        if (threadIdx.x < o) red[threadIdx.x] += red[threadIdx.x + o];
        __syncthreads();
    }
    if (threadIdx.x < 32) {
        float v = red[threadIdx.x];
        for (int o = 16; o; o >>= 1)
            v += __shfl_xor_sync(0xFFFFFFFFu, v, o);
        if (threadIdx.x == 0) {
            atomicAdd(&g_acc, (double)v);
            __threadfence();
            unsigned int tkt = atomicAdd(&g_ticket, 1u);
            if (tkt == gridDim.x - 1) {
                out[0] = (float)(g_acc / (double)B);
                g_acc = 0.0;
                g_ticket = 0;
            }
        }
    }
}

extern "C" void kernel_launch(void* const* d_in, const int* in_sizes, int n_in,
                              void* d_out, int out_size) {
    const float*         pred   = (const float*)d_in[0];
    // d_in[1] = target_abs (unused by the reference)
    const unsigned char* mask   = (const unsigned char*)d_in[2];
    const float*         runway = (const float*)d_in[3];
    float*               out    = (float*)d_out;

    int B = in_sizes[3] / 4;          // runway is (B, 4)
    int H = in_sizes[2] / B;          // mask is (B, H)

    if (H == 120) {
        int threads_needed = B * 4;
        int blocks = (threads_needed + TPB - 1) / TPB;
        runway_loss_h120<<<blocks, TPB>>>(pred, mask, runway, out, B);
    } else {
        int blocks = (B + TPB - 1) / TPB;
        runway_loss_generic<<<blocks, TPB>>>(pred, mask, runway, out, B, H);
    }
}